// round 4
// baseline (speedup 1.0000x reference)
#include <cuda_runtime.h>

// ---------------------------------------------------------------------------
// Persistent fused LSTM: T=2048, B=256, H=128, IN_DIM=1, output feedback.
// 128 CTAs x 512 threads; CTA c owns batches (2c, 2c+1).
// W_hh rows 0..255 (i,f) in registers (64 floats/thread), rows 256..511 (g,o)
// in bank-exact padded SMEM. Packed fma.rn.f32x2. 4-way k-split per row pair.
// R3: 16 warps for latency hiding, 2 barriers/step, register x feedback.
// ---------------------------------------------------------------------------

typedef unsigned long long ull;

#define THREADS 512
#define T_STEPS 2048
#define NB      256

// SMEM layout (float offsets)
#define W_PITCH  152          // floats per weight row (4 quarters of 36 + pad)
#define KQ       36           // k-quarter stride in padded layout
#define WS_OFF   0            // 256 rows x 152 = 38912 floats
#define GBUF     38912        // gates: 2 batches x 512
#define HBUF     39936        // h: 2 batches x 148 (padded quarters)
#define H_PITCH  148
#define WLIN     40232        // 128
#define YBUF     40360        // 8 per-warp partials (warps 0..7)
#define SMEM_FLOATS 40384
#define SMEM_BYTES  (SMEM_FLOATS * 4)

__device__ __forceinline__ ull pk2(float x, float y) {
    ull r; asm("mov.b64 %0, {%1, %2};" : "=l"(r) : "f"(x), "f"(y)); return r;
}
__device__ __forceinline__ float2 upk2(ull v) {
    float2 f; asm("mov.b64 {%0, %1}, %2;" : "=f"(f.x), "=f"(f.y) : "l"(v)); return f;
}
__device__ __forceinline__ ull ffma2(ull a, ull b, ull c) {
    ull d; asm("fma.rn.f32x2 %0, %1, %2, %3;" : "=l"(d) : "l"(a), "l"(b), "l"(c)); return d;
}
__device__ __forceinline__ float sigf(float x)  { return __fdividef(1.0f, 1.0f + __expf(-x)); }
__device__ __forceinline__ float tanhx(float x) { return __fdividef(2.0f, 1.0f + __expf(-2.0f * x)) - 1.0f; }

// padded indices
__device__ __forceinline__ int ws_idx(int row, int k) {         // row 0..255 (g,o block)
    return WS_OFF + row * W_PITCH + (k >> 5) * KQ + (k & 31);
}
__device__ __forceinline__ int hb_idx(int b, int k) {
    return HBUF + b * H_PITCH + (k >> 5) * KQ + (k & 31);
}

__global__ void __launch_bounds__(THREADS, 1)
lstm_seq_kernel(float* __restrict__ out,
                const int*   __restrict__ label,
                const float* __restrict__ h0,
                const float* __restrict__ W_ih,
                const float* __restrict__ W_hh,
                const float* __restrict__ b_ih,
                const float* __restrict__ b_hh,
                const float* __restrict__ W_lin,
                const float* __restrict__ b_lin)
{
    extern __shared__ float sm[];
    const int t   = threadIdx.x;
    const int cta = blockIdx.x;
    const int p   = t >> 2;       // row pair 0..127
    const int ks  = t & 3;        // k quarter 0..3
    const int kofs  = ks * KQ;    // padded quarter offset
    const int kbase = ks * 32;    // logical k base
    const float bsel = (ks == 0) ? 1.0f : 0.0f;   // bias counted once per 4-lane group

    // ---- one-time init -----------------------------------------------------
    for (int idx = t; idx < 256 * 128; idx += THREADS) {
        int row = idx >> 7, k = idx & 127;
        sm[ws_idx(row, k)] = W_hh[(256 + row) * 128 + k];
    }
    if (t < 128) sm[WLIN + t] = W_lin[t];
    if (t < 256) {                 // initial h from h0[0, label[b], :]
        int b = t >> 7, j = t & 127;
        int lab = label[2 * cta + b];
        sm[hb_idx(b, j)] = h0[lab * 128 + j];
    }

    // Register weights: rows 2p, 2p+1 (i,f gates), this thread's k quarter.
    float4 wreg[2][8];
#pragma unroll
    for (int rr = 0; rr < 2; ++rr) {
        const float4* wsrc = (const float4*)(W_hh + (2 * p + rr) * 128 + kbase);
#pragma unroll
        for (int c = 0; c < 8; ++c) wreg[rr][c] = wsrc[c];
    }

    // bias + W_ih for this thread's 4 gate rows {2p, 2p+1, 256+2p, 257+2p}
    float biasv[4], wihv[4];
    {
        int rows[4] = {2 * p, 2 * p + 1, 256 + 2 * p, 257 + 2 * p};
#pragma unroll
        for (int q = 0; q < 4; ++q) {
            biasv[q] = b_ih[rows[q]] + b_hh[rows[q]];
            wihv[q]  = W_ih[rows[q]];
        }
    }
    const float blin = b_lin[0];
    float c_state = 0.0f;          // cell state for (b = t>>7, j = t&127), t<256

    const float* wsm0 = sm + WS_OFF + (2 * p) * W_PITCH + kofs;  // smem row 256+2p
    const float* wsm1 = wsm0 + W_PITCH;                          // smem row 257+2p
    const float* hp0  = sm + HBUF + kofs;
    const float* hp1  = hp0 + H_PITCH;

    float x0 = 0.0f, x1 = 0.0f;    // fed-back inputs, live in registers

    __syncthreads();

    // ---- 2048-step recurrence ----------------------------------------------
    for (int step = 0; step < T_STEPS; ++step) {
        if (step > 0) {
            // every thread redundantly folds the 8 warp partials (cheap,
            // removes a barrier + 2-thread serialization)
            x0 = sm[YBUF + 0] + sm[YBUF + 1] + sm[YBUF + 2] + sm[YBUF + 3] + blin;
            x1 = sm[YBUF + 4] + sm[YBUF + 5] + sm[YBUF + 6] + sm[YBUF + 7] + blin;
            if (t < 2) out[(step - 1) * NB + 2 * cta + t] = (t ? x1 : x0);
        }

        // ====== matvec: gates = W_hh h + x W_ih + b ======
        ull acc[4][2];
#pragma unroll
        for (int q = 0; q < 4; ++q) {
            acc[q][0] = pk2(bsel * fmaf(x0, wihv[q], biasv[q]), 0.0f);
            acc[q][1] = pk2(bsel * fmaf(x1, wihv[q], biasv[q]), 0.0f);
        }

#pragma unroll
        for (int c = 0; c < 8; ++c) {
            float4 hv0 = *(const float4*)(hp0 + c * 4);
            float4 hv1 = *(const float4*)(hp1 + c * 4);
            float4 wv0 = wreg[0][c];
            float4 wv1 = wreg[1][c];
            float4 wv2 = *(const float4*)(wsm0 + c * 4);
            float4 wv3 = *(const float4*)(wsm1 + c * 4);

            ull h0a = pk2(hv0.x, hv0.y), h0b = pk2(hv0.z, hv0.w);
            ull h1a = pk2(hv1.x, hv1.y), h1b = pk2(hv1.z, hv1.w);
            ull w0a = pk2(wv0.x, wv0.y), w0b = pk2(wv0.z, wv0.w);
            ull w1a = pk2(wv1.x, wv1.y), w1b = pk2(wv1.z, wv1.w);
            ull w2a = pk2(wv2.x, wv2.y), w2b = pk2(wv2.z, wv2.w);
            ull w3a = pk2(wv3.x, wv3.y), w3b = pk2(wv3.z, wv3.w);

#define DO_ROW(q, wa, wb)                                   \
            acc[q][0] = ffma2(wa, h0a, acc[q][0]);          \
            acc[q][0] = ffma2(wb, h0b, acc[q][0]);          \
            acc[q][1] = ffma2(wa, h1a, acc[q][1]);          \
            acc[q][1] = ffma2(wb, h1b, acc[q][1]);
            DO_ROW(0, w0a, w0b)
            DO_ROW(1, w1a, w1b)
            DO_ROW(2, w2a, w2b)
            DO_ROW(3, w3a, w3b)
#undef DO_ROW
        }

        // reduce f32x2 lanes + 4 complementary k-quarter lanes (t^1, t^2)
        float s[4][2];
#pragma unroll
        for (int q = 0; q < 4; ++q) {
#pragma unroll
            for (int b = 0; b < 2; ++b) {
                float2 a = upk2(acc[q][b]);
                float v = a.x + a.y;
                v += __shfl_xor_sync(0xffffffffu, v, 1);
                v += __shfl_xor_sync(0xffffffffu, v, 2);
                s[q][b] = v;
            }
        }
        {   // lane ks writes its designated row (q = ks), both batches
            int row = (ks < 2) ? (2 * p + ks) : (256 + 2 * p + (ks - 2));
            sm[GBUF +       row] = s[ks][0];
            sm[GBUF + 512 + row] = s[ks][1];
        }
        __syncthreads();   // GBUF ready; matvec reads of HBUF/YBUF complete

        // ====== update: c,h,y for (b = t>>7, j = t&127), first 256 threads ==
        if (t < 256) {
            int b = t >> 7, j = t & 127;
            const float* gb = sm + GBUF + b * 512 + j;
            float gi = gb[0], gf = gb[128], gg = gb[256], go = gb[384];
            float iv = sigf(gi);
            float fv = sigf(gf);
            float gv = tanhx(gg);
            float ov = sigf(go);
            c_state = fv * c_state + iv * gv;
            float hn = ov * tanhx(c_state);
            sm[hb_idx(b, j)] = hn;

            float py = hn * sm[WLIN + j];
#pragma unroll
            for (int off = 16; off; off >>= 1)
                py += __shfl_down_sync(0xffffffffu, py, off);
            if ((t & 31) == 0) sm[YBUF + (t >> 5)] = py;  // warps 0..7
        }
        __syncthreads();   // HBUF + YBUF ready for next step
    }

    // final output (YBUF from last step is visible after the loop's last sync)
    if (t < 2) {
        float y = sm[YBUF + 4 * t + 0] + sm[YBUF + 4 * t + 1] +
                  sm[YBUF + 4 * t + 2] + sm[YBUF + 4 * t + 3] + blin;
        out[(T_STEPS - 1) * NB + 2 * cta + t] = y;
    }
}

extern "C" void kernel_launch(void* const* d_in, const int* in_sizes, int n_in,
                              void* d_out, int out_size) {
    // metadata order: input, label, h0, W_ih, W_hh, b_ih, b_hh, W_lin, b_lin
    const int*   label  = (const int*)  d_in[1];
    const float* h0     = (const float*)d_in[2];
    const float* W_ih   = (const float*)d_in[3];
    const float* W_hh   = (const float*)d_in[4];
    const float* b_ih   = (const float*)d_in[5];
    const float* b_hh   = (const float*)d_in[6];
    const float* W_lin  = (const float*)d_in[7];
    const float* b_lin  = (const float*)d_in[8];
    float* out = (float*)d_out;

    cudaFuncSetAttribute(lstm_seq_kernel,
                         cudaFuncAttributeMaxDynamicSharedMemorySize, SMEM_BYTES);
    lstm_seq_kernel<<<128, THREADS, SMEM_BYTES>>>(out, label, h0, W_ih, W_hh,
                                                  b_ih, b_hh, W_lin, b_lin);
}

// round 5
// speedup vs baseline: 1.0478x; 1.0478x over previous
#include <cuda_runtime.h>

// ---------------------------------------------------------------------------
// Persistent fused LSTM: T=2048, B=256, H=128, IN_DIM=1, output feedback.
// 128 CTAs x 512 threads; CTA c owns batches (2c, 2c+1).
// Thread (p = t>>2, ks = t&3) owns gate rows {2p,2p+1} (reg weights, packed
// f32x2) and {256+2p,257+2p} (SMEM weights), k-quarter ks (32 k values).
// R4: no spills (pre-packed ull weights, ull2 loads), bias/input folded into
// update phase, xor1-only reduction with GBUF half-sums, bank-exact layouts.
// ---------------------------------------------------------------------------

typedef unsigned long long ull;

#define THREADS 512
#define T_STEPS 2048
#define NB      256

// SMEM layout (float offsets)
#define KQ       36                    // k-quarter stride (32 + 4 pad)
#define W_PITCH  152                   // weight row pitch (4*36 + 8 pad -> granule shift 4)
#define WS_OFF   0                     // 256 rows x 152 = 38912
#define GBUF     38912                 // partial gates: [half][b][512], strides 1040/513
#define GB_HS    1040
#define GB_BS    513
#define HBUF     (GBUF + 2*GB_HS)      // 40992: h, 2 batches x 144
#define H_PITCH  144
#define WLIN     (HBUF + 2*H_PITCH)    // 41280
#define BIASB    (WLIN + 128)          // 41408: b_ih+b_hh, 512
#define WIHB     (BIASB + 512)         // 41920: W_ih, 512
#define YBUF     (WIHB + 512)          // 42432: 8 per-warp y partials
#define SMEM_FLOATS (YBUF + 8)
#define SMEM_BYTES  (SMEM_FLOATS * 4)

__device__ __forceinline__ ull pk2(float x, float y) {
    ull r; asm("mov.b64 %0, {%1, %2};" : "=l"(r) : "f"(x), "f"(y)); return r;
}
__device__ __forceinline__ float2 upk2(ull v) {
    float2 f; asm("mov.b64 {%0, %1}, %2;" : "=f"(f.x), "=f"(f.y) : "l"(v)); return f;
}
__device__ __forceinline__ ull ffma2(ull a, ull b, ull c) {
    ull d; asm("fma.rn.f32x2 %0, %1, %2, %3;" : "=l"(d) : "l"(a), "l"(b), "l"(c)); return d;
}
__device__ __forceinline__ float sigf(float x)  { return __fdividef(1.0f, 1.0f + __expf(-x)); }
__device__ __forceinline__ float tanhx(float x) { return __fdividef(2.0f, 1.0f + __expf(-2.0f * x)) - 1.0f; }

__global__ void __launch_bounds__(THREADS, 1)
lstm_seq_kernel(float* __restrict__ out,
                const int*   __restrict__ label,
                const float* __restrict__ h0,
                const float* __restrict__ W_ih,
                const float* __restrict__ W_hh,
                const float* __restrict__ b_ih,
                const float* __restrict__ b_hh,
                const float* __restrict__ W_lin,
                const float* __restrict__ b_lin)
{
    extern __shared__ float sm[];
    const int t   = threadIdx.x;
    const int cta = blockIdx.x;
    const int p   = t >> 2;       // row pair 0..127
    const int ks  = t & 3;        // k quarter 0..3

    // ---- one-time init -----------------------------------------------------
    for (int idx = t; idx < 256 * 128; idx += THREADS) {
        int r = idx >> 7, k = idx & 127;
        sm[WS_OFF + r * W_PITCH + (k >> 5) * KQ + (k & 31)] = W_hh[(256 + r) * 128 + k];
    }
    if (t < 128) sm[WLIN + t] = W_lin[t];
    if (t < 256) {                 // initial h from h0[0, label[b], :]
        int b = t >> 7, j = t & 127;
        int lab = label[2 * cta + b];
        sm[HBUF + b * H_PITCH + (j >> 5) * KQ + (j & 31)] = h0[lab * 128 + j];
    }
    {   // bias + W_ih tables (consumed in update phase)
        sm[BIASB + t] = b_ih[t] + b_hh[t];
        sm[WIHB  + t] = W_ih[t];
    }

    // Register weights: rows 2p, 2p+1 (i,f gates), k in [ks*32, ks*32+32),
    // pre-packed as f32x2 (ull) -- no per-step packing movs.
    ull wreg[2][16];
#pragma unroll
    for (int rr = 0; rr < 2; ++rr) {
        const float2* wsrc = (const float2*)(W_hh + (2 * p + rr) * 128 + ks * 32);
#pragma unroll
        for (int c = 0; c < 16; ++c) {
            float2 w = wsrc[c];
            wreg[rr][c] = pk2(w.x, w.y);
        }
    }

    const float blin = b_lin[0];
    float c_state = 0.0f;          // cell state for (b = t>>7, j = t&127), t<256
    float x0 = 0.0f, x1 = 0.0f;    // fed-back inputs (registers)

    // matvec base pointers (constant across steps)
    const ulonglong2* W2 = (const ulonglong2*)(sm + WS_OFF + (2 * p) * W_PITCH + ks * KQ);
    const ulonglong2* W3 = (const ulonglong2*)(sm + WS_OFF + (2 * p + 1) * W_PITCH + ks * KQ);
    const ulonglong2* H0 = (const ulonglong2*)(sm + HBUF + ks * KQ);
    const ulonglong2* H1 = (const ulonglong2*)(sm + HBUF + H_PITCH + ks * KQ);
    // GBUF write base for this lane: half = ks>>1, batch = ks&1
    float* gw = sm + GBUF + (ks >> 1) * GB_HS + (ks & 1) * GB_BS;

    __syncthreads();

    // ---- 2048-step recurrence ----------------------------------------------
    for (int step = 0; step < T_STEPS; ++step) {
        if (step > 0) {
            x0 = sm[YBUF + 0] + sm[YBUF + 1] + sm[YBUF + 2] + sm[YBUF + 3] + blin;
            x1 = sm[YBUF + 4] + sm[YBUF + 5] + sm[YBUF + 6] + sm[YBUF + 7] + blin;
            if (t < 2) out[(step - 1) * NB + 2 * cta + t] = (t ? x1 : x0);
        }

        // ====== matvec: partial gates = W_hh[:, kq] . h[kq] ======
        ull a00 = 0, a01 = 0, a10 = 0, a11 = 0;   // rows 2p, 2p+1      (reg W)
        ull a20 = 0, a21 = 0, a30 = 0, a31 = 0;   // rows 256+2p,257+2p (smem W)

#pragma unroll
        for (int c = 0; c < 8; ++c) {
            ulonglong2 h0v = H0[c];
            ulonglong2 h1v = H1[c];
            ulonglong2 w2  = W2[c];
            ulonglong2 w3  = W3[c];
            ull wr0a = wreg[0][2 * c], wr0b = wreg[0][2 * c + 1];
            ull wr1a = wreg[1][2 * c], wr1b = wreg[1][2 * c + 1];

            a00 = ffma2(wr0a, h0v.x, a00); a00 = ffma2(wr0b, h0v.y, a00);
            a01 = ffma2(wr0a, h1v.x, a01); a01 = ffma2(wr0b, h1v.y, a01);
            a10 = ffma2(wr1a, h0v.x, a10); a10 = ffma2(wr1b, h0v.y, a10);
            a11 = ffma2(wr1a, h1v.x, a11); a11 = ffma2(wr1b, h1v.y, a11);
            a20 = ffma2(w2.x,  h0v.x, a20); a20 = ffma2(w2.y,  h0v.y, a20);
            a21 = ffma2(w2.x,  h1v.x, a21); a21 = ffma2(w2.y,  h1v.y, a21);
            a30 = ffma2(w3.x,  h0v.x, a30); a30 = ffma2(w3.y,  h0v.y, a30);
            a31 = ffma2(w3.x,  h1v.x, a31); a31 = ffma2(w3.y,  h1v.y, a31);
        }

        // fold f32x2 lanes, combine k-quarter pairs (xor 1), store half-sums.
        // After xor1, lane pair (ks,ks^1) holds identical sums for its k-half;
        // lane ks stores batch (ks&1) into GBUF half (ks>>1).
        {
            float v0, v1, v2, v3;
            {
                float2 f00 = upk2(a00), f01 = upk2(a01);
                float2 f10 = upk2(a10), f11 = upk2(a11);
                float2 f20 = upk2(a20), f21 = upk2(a21);
                float2 f30 = upk2(a30), f31 = upk2(a31);
                float s00 = f00.x + f00.y, s01 = f01.x + f01.y;
                float s10 = f10.x + f10.y, s11 = f11.x + f11.y;
                float s20 = f20.x + f20.y, s21 = f21.x + f21.y;
                float s30 = f30.x + f30.y, s31 = f31.x + f31.y;
                // exchange batch values so lane (ks&1)==0 accumulates b0, etc.
                // simpler: sum both k-quarters of the pair for ALL 8 values,
                // then lane picks its batch.
                s00 += __shfl_xor_sync(0xffffffffu, s00, 1);
                s01 += __shfl_xor_sync(0xffffffffu, s01, 1);
                s10 += __shfl_xor_sync(0xffffffffu, s10, 1);
                s11 += __shfl_xor_sync(0xffffffffu, s11, 1);
                s20 += __shfl_xor_sync(0xffffffffu, s20, 1);
                s21 += __shfl_xor_sync(0xffffffffu, s21, 1);
                s30 += __shfl_xor_sync(0xffffffffu, s30, 1);
                s31 += __shfl_xor_sync(0xffffffffu, s31, 1);
                if (ks & 1) { v0 = s01; v1 = s11; v2 = s21; v3 = s31; }
                else        { v0 = s00; v1 = s10; v2 = s20; v3 = s30; }
            }
            gw[2 * p]           = v0;
            gw[2 * p + 1]       = v1;
            gw[256 + 2 * p]     = v2;
            gw[256 + 2 * p + 1] = v3;
        }
        __syncthreads();   // GBUF ready; HBUF/YBUF reads of this step complete

        // ====== update: c,h,y for (b = t>>7, j = t&127) ======
        if (t < 256) {
            int b = t >> 7, j = t & 127;
            const float* gl = sm + GBUF + b * GB_BS;           // k-low half
            const float* gh = gl + GB_HS;                      // k-high half
            float xb = b ? x1 : x0;
            float gi = gl[j]       + gh[j]       + fmaf(xb, sm[WIHB + j],       sm[BIASB + j]);
            float gf = gl[128 + j] + gh[128 + j] + fmaf(xb, sm[WIHB + 128 + j], sm[BIASB + 128 + j]);
            float gg = gl[256 + j] + gh[256 + j] + fmaf(xb, sm[WIHB + 256 + j], sm[BIASB + 256 + j]);
            float go = gl[384 + j] + gh[384 + j] + fmaf(xb, sm[WIHB + 384 + j], sm[BIASB + 384 + j]);

            float iv = sigf(gi);
            float fv = sigf(gf);
            float gv = tanhx(gg);
            float ov = sigf(go);
            c_state = fv * c_state + iv * gv;
            float hn = ov * tanhx(c_state);
            sm[HBUF + b * H_PITCH + (j >> 5) * KQ + (j & 31)] = hn;

            float py = hn * sm[WLIN + j];
#pragma unroll
            for (int off = 16; off; off >>= 1)
                py += __shfl_down_sync(0xffffffffu, py, off);
            if ((t & 31) == 0) sm[YBUF + (t >> 5)] = py;  // warps 0..7
        }
        __syncthreads();   // HBUF + YBUF ready for next step
    }

    // final step's output
    if (t < 2) {
        float y = sm[YBUF + 4 * t + 0] + sm[YBUF + 4 * t + 1] +
                  sm[YBUF + 4 * t + 2] + sm[YBUF + 4 * t + 3] + blin;
        out[(T_STEPS - 1) * NB + 2 * cta + t] = y;
    }
}

extern "C" void kernel_launch(void* const* d_in, const int* in_sizes, int n_in,
                              void* d_out, int out_size) {
    // metadata order: input, label, h0, W_ih, W_hh, b_ih, b_hh, W_lin, b_lin
    const int*   label  = (const int*)  d_in[1];
    const float* h0     = (const float*)d_in[2];
    const float* W_ih   = (const float*)d_in[3];
    const float* W_hh   = (const float*)d_in[4];
    const float* b_ih   = (const float*)d_in[5];
    const float* b_hh   = (const float*)d_in[6];
    const float* W_lin  = (const float*)d_in[7];
    const float* b_lin  = (const float*)d_in[8];
    float* out = (float*)d_out;

    cudaFuncSetAttribute(lstm_seq_kernel,
                         cudaFuncAttributeMaxDynamicSharedMemorySize, SMEM_BYTES);
    lstm_seq_kernel<<<128, THREADS, SMEM_BYTES>>>(out, label, h0, W_ih, W_hh,
                                                  b_ih, b_hh, W_lin, b_lin);
}

// round 6
// speedup vs baseline: 1.3349x; 1.2740x over previous
#include <cuda_runtime.h>

// ---------------------------------------------------------------------------
// Persistent fused LSTM: T=2048, B=256, H=128, IN_DIM=1, output feedback.
// 128 CTAs x 256 threads; CTA c owns batches (2c, 2c+1).
// Thread (p = t>>1, ks = t&1): gate rows {2p,2p+1} with weights in registers
// (pre-packed f32x2, 128 regs) and rows {256+2p,257+2p} streamed from SMEM;
// k-half ks (64 values). No matvec shuffles: per-half partials to GBUF,
// update phase sums halves + bias + x*W_ih. 2 barriers/step; x-feedback via
// double-buffered YBUF inside the update phase.
// ---------------------------------------------------------------------------

typedef unsigned long long ull;

#define THREADS 256
#define T_STEPS 2048
#define NB      256

// SMEM layout (float offsets)
#define KH       68                    // k-half stride (64 + 4 pad)
#define W_PITCH  140                   // weight/h row pitch (2*68 + 4)
#define WS_OFF   0                     // 256 rows x 140 = 35840
#define GBUF     35840                 // partial gates: [half][batch][512]
#define GB_BS    520                   // batch stride (even, 8B-align for STS.64)
#define GB_HS    1044                  // half stride (even)
#define HBUF     (GBUF + 2*GB_HS)      // 37928: h, 2 batches x 140
#define H_PITCH  140
#define WLIN     (HBUF + 2*H_PITCH)    // 38208
#define BIASB    (WLIN + 128)          // 38336: b_ih + b_hh (512)
#define WIHB     (BIASB + 512)         // 38848: W_ih (512)
#define YBUF     (WIHB + 512)          // 39360: 2 slots x 8 warp partials
#define SMEM_FLOATS (YBUF + 16)
#define SMEM_BYTES  (SMEM_FLOATS * 4)

__device__ __forceinline__ ull pk2(float x, float y) {
    ull r; asm("mov.b64 %0, {%1, %2};" : "=l"(r) : "f"(x), "f"(y)); return r;
}
__device__ __forceinline__ float2 upk2(ull v) {
    float2 f; asm("mov.b64 {%0, %1}, %2;" : "=f"(f.x), "=f"(f.y) : "l"(v)); return f;
}
__device__ __forceinline__ ull ffma2(ull a, ull b, ull c) {
    ull d; asm("fma.rn.f32x2 %0, %1, %2, %3;" : "=l"(d) : "l"(a), "l"(b), "l"(c)); return d;
}
__device__ __forceinline__ float sigf(float x)  { return __fdividef(1.0f, 1.0f + __expf(-x)); }
__device__ __forceinline__ float tanhx(float x) { return __fdividef(2.0f, 1.0f + __expf(-2.0f * x)) - 1.0f; }

__global__ void __launch_bounds__(THREADS, 1)
lstm_seq_kernel(float* __restrict__ out,
                const int*   __restrict__ label,
                const float* __restrict__ h0,
                const float* __restrict__ W_ih,
                const float* __restrict__ W_hh,
                const float* __restrict__ b_ih,
                const float* __restrict__ b_hh,
                const float* __restrict__ W_lin,
                const float* __restrict__ b_lin)
{
    extern __shared__ float sm[];
    const int t   = threadIdx.x;
    const int cta = blockIdx.x;
    const int p   = t >> 1;       // row pair 0..127
    const int ks  = t & 1;        // k half 0..1

    // ---- one-time init -----------------------------------------------------
    for (int idx = t; idx < 256 * 128; idx += THREADS) {
        int r = idx >> 7, k = idx & 127;
        sm[WS_OFF + r * W_PITCH + (k >> 6) * KH + (k & 63)] = W_hh[(256 + r) * 128 + k];
    }
    if (t < 128) sm[WLIN + t] = W_lin[t];
    {   // initial h from h0[0, label[b], :]
        int b = t >> 7, j = t & 127;
        int lab = label[2 * cta + b];
        sm[HBUF + b * H_PITCH + (j >> 6) * KH + (j & 63)] = h0[lab * 128 + j];
    }
    sm[BIASB + t]       = b_ih[t]       + b_hh[t];
    sm[BIASB + 256 + t] = b_ih[256 + t] + b_hh[256 + t];
    sm[WIHB  + t]       = W_ih[t];
    sm[WIHB  + 256 + t] = W_ih[256 + t];

    // Register weights: rows 2p,2p+1 (i,f gates), k in [ks*64, ks*64+64),
    // pre-packed f32x2 (64 ull = 128 regs).
    ull wreg[2][32];
#pragma unroll
    for (int rr = 0; rr < 2; ++rr) {
        const float2* wsrc = (const float2*)(W_hh + (2 * p + rr) * 128 + ks * 64);
#pragma unroll
        for (int c = 0; c < 32; ++c) {
            float2 w = wsrc[c];
            wreg[rr][c] = pk2(w.x, w.y);
        }
    }

    const float blin = b_lin[0];
    float c_state = 0.0f;          // cell state for (b = t>>7, j = t&127)

    // matvec base pointers (constant across steps)
    const ulonglong2* W2 = (const ulonglong2*)(sm + WS_OFF + (2 * p)     * W_PITCH + ks * KH);
    const ulonglong2* W3 = (const ulonglong2*)(sm + WS_OFF + (2 * p + 1) * W_PITCH + ks * KH);
    const ulonglong2* H0 = (const ulonglong2*)(sm + HBUF + ks * KH);
    const ulonglong2* H1 = (const ulonglong2*)(sm + HBUF + H_PITCH + ks * KH);
    float2* gw = (float2*)(sm + GBUF + ks * GB_HS);   // this lane's half

    // update-phase constants
    const int  ub = t >> 7;                 // batch this thread updates
    const int  uj = t & 127;                // hidden index
    const int  hwr = HBUF + ub * H_PITCH + ((uj >> 6) * KH) + (uj & 63);
    const float wlin_j = W_lin[uj];
    const int  ybase = ub * 4;              // YBUF partial range for this batch

    __syncthreads();

    // ---- 2048-step recurrence ----------------------------------------------
    for (int step = 0; step < T_STEPS; ++step) {
        // ====== matvec: per-half partial gates = W_hh[:, kh] . h[kh] ======
        ull a00 = 0, a01 = 0, a10 = 0, a11 = 0;   // rows 2p,2p+1      (reg W)
        ull a20 = 0, a21 = 0, a30 = 0, a31 = 0;   // rows 256+2p,257+2p (smem W)

#pragma unroll
        for (int c = 0; c < 16; ++c) {
            ulonglong2 h0v = H0[c];
            ulonglong2 h1v = H1[c];
            ulonglong2 w2  = W2[c];
            ulonglong2 w3  = W3[c];
            ull wr0a = wreg[0][2 * c], wr0b = wreg[0][2 * c + 1];
            ull wr1a = wreg[1][2 * c], wr1b = wreg[1][2 * c + 1];

            a00 = ffma2(wr0a, h0v.x, a00); a00 = ffma2(wr0b, h0v.y, a00);
            a01 = ffma2(wr0a, h1v.x, a01); a01 = ffma2(wr0b, h1v.y, a01);
            a10 = ffma2(wr1a, h0v.x, a10); a10 = ffma2(wr1b, h0v.y, a10);
            a11 = ffma2(wr1a, h1v.x, a11); a11 = ffma2(wr1b, h1v.y, a11);
            a20 = ffma2(w2.x,  h0v.x, a20); a20 = ffma2(w2.y,  h0v.y, a20);
            a21 = ffma2(w2.x,  h1v.x, a21); a21 = ffma2(w2.y,  h1v.y, a21);
            a30 = ffma2(w3.x,  h0v.x, a30); a30 = ffma2(w3.y,  h0v.y, a30);
            a31 = ffma2(w3.x,  h1v.x, a31); a31 = ffma2(w3.y,  h1v.y, a31);
        }

        // fold f32x2 lanes; store per-half partials (no shuffles)
        {
            float2 f;
            float s00, s01, s10, s11, s20, s21, s30, s31;
            f = upk2(a00); s00 = f.x + f.y;
            f = upk2(a01); s01 = f.x + f.y;
            f = upk2(a10); s10 = f.x + f.y;
            f = upk2(a11); s11 = f.x + f.y;
            f = upk2(a20); s20 = f.x + f.y;
            f = upk2(a21); s21 = f.x + f.y;
            f = upk2(a30); s30 = f.x + f.y;
            f = upk2(a31); s31 = f.x + f.y;
            gw[p]                      = make_float2(s00, s10);   // b0, rows 2p,2p+1
            gw[(GB_BS >> 1) + p]       = make_float2(s01, s11);   // b1
            gw[128 + p]                = make_float2(s20, s30);   // b0, rows 256+..
            gw[(GB_BS >> 1) + 128 + p] = make_float2(s21, s31);   // b1
        }
        __syncthreads();   // GBUF ready; HBUF reads complete

        // ====== update: x-fold, gates, c/h, y-reduce (all 256 threads) ======
        {
            const int yslot = YBUF + (step & 1) * 8;
            float xb = 0.0f;
            if (step > 0) {
                xb = sm[yslot + ybase] + sm[yslot + ybase + 1] +
                     sm[yslot + ybase + 2] + sm[yslot + ybase + 3] + blin;
                if (uj == 0) out[(step - 1) * NB + 2 * cta + ub] = xb;
            }

            const float* gl = sm + GBUF + ub * GB_BS;     // k-low half
            const float* gh = gl + GB_HS;                 // k-high half
            float gi = gl[uj]       + gh[uj]       + fmaf(xb, sm[WIHB + uj],       sm[BIASB + uj]);
            float gf = gl[128 + uj] + gh[128 + uj] + fmaf(xb, sm[WIHB + 128 + uj], sm[BIASB + 128 + uj]);
            float gg = gl[256 + uj] + gh[256 + uj] + fmaf(xb, sm[WIHB + 256 + uj], sm[BIASB + 256 + uj]);
            float go = gl[384 + uj] + gh[384 + uj] + fmaf(xb, sm[WIHB + 384 + uj], sm[BIASB + 384 + uj]);

            float iv = sigf(gi);
            float fv = sigf(gf);
            float gv = tanhx(gg);
            float ov = sigf(go);
            c_state = fv * c_state + iv * gv;
            float hn = ov * tanhx(c_state);
            sm[hwr] = hn;

            float py = hn * wlin_j;
#pragma unroll
            for (int off = 16; off; off >>= 1)
                py += __shfl_down_sync(0xffffffffu, py, off);
            if ((t & 31) == 0)
                sm[YBUF + ((step + 1) & 1) * 8 + (t >> 5)] = py;
        }
        __syncthreads();   // HBUF + YBUF ready for next step
    }

    // final step's output: y_{T-1} lives in YBUF slot (T_STEPS & 1)
    if (t < 2) {
        const int yslot = YBUF + (T_STEPS & 1) * 8;
        float y = sm[yslot + 4 * t + 0] + sm[yslot + 4 * t + 1] +
                  sm[yslot + 4 * t + 2] + sm[yslot + 4 * t + 3] + blin;
        out[(T_STEPS - 1) * NB + 2 * cta + t] = y;
    }
}

extern "C" void kernel_launch(void* const* d_in, const int* in_sizes, int n_in,
                              void* d_out, int out_size) {
    // metadata order: input, label, h0, W_ih, W_hh, b_ih, b_hh, W_lin, b_lin
    const int*   label  = (const int*)  d_in[1];
    const float* h0     = (const float*)d_in[2];
    const float* W_ih   = (const float*)d_in[3];
    const float* W_hh   = (const float*)d_in[4];
    const float* b_ih   = (const float*)d_in[5];
    const float* b_hh   = (const float*)d_in[6];
    const float* W_lin  = (const float*)d_in[7];
    const float* b_lin  = (const float*)d_in[8];
    float* out = (float*)d_out;

    cudaFuncSetAttribute(lstm_seq_kernel,
                         cudaFuncAttributeMaxDynamicSharedMemorySize, SMEM_BYTES);
    lstm_seq_kernel<<<128, THREADS, SMEM_BYTES>>>(out, label, h0, W_ih, W_hh,
                                                  b_ih, b_hh, W_lin, b_lin);
}